// round 6
// baseline (speedup 1.0000x reference)
#include <cuda_runtime.h>

// ---------------------------------------------------------------------------
// GCN: 3x (GEMM -> GCN-normalized aggregate w/ self loops -> BN(eval)+ReLU)
//      -> global mean+max pool per graph -> 2-layer MLP head.
// Strategy: build CSR indexed by TARGET node once per call (int atomics only),
// then every aggregate layer is a pure gather (no float atomics). The 25.6MB
// feature buffer lives in L2, so aggregates are L2-bandwidth bound.
// ---------------------------------------------------------------------------

#define NN   100000
#define EE   1600000
#define GG   512
#define INF  26
#define HF   64
#define EPSV 1e-5f

// Scratch (device globals; no runtime allocation allowed)
__device__ float    g_t[(size_t)NN * HF];   // transformed features (GEMM out)
__device__ float    g_h[(size_t)NN * HF];   // layer activations
__device__ int      g_deg[NN];              // in-degree incl. self loop
__device__ float    g_dinv[NN];             // deg^{-1/2}
__device__ int      g_rowptr[NN + 1];       // CSR row pointers (by target)
__device__ int      g_cursor[NN];           // fill cursors
__device__ int      g_csr[EE];              // source node per CSR slot
__device__ int      g_bsum[128];            // scan block sums
__device__ float    g_psum[GG * HF];        // pooling: sum
__device__ unsigned g_pmax[GG * HF];        // pooling: max (float bits, h>=0)
__device__ int      g_pcnt[GG];             // pooling: node count

// --------------------------- setup kernels --------------------------------

__global__ void init_kernel() {
    int i = blockIdx.x * blockDim.x + threadIdx.x;
    if (i < NN) g_deg[i] = 1;                       // self loop
    if (i < GG * HF) { g_psum[i] = 0.f; g_pmax[i] = 0u; }
    if (i < GG) g_pcnt[i] = 0;
}

__global__ void deg_kernel(const int* __restrict__ ecol) {
    int e = blockIdx.x * blockDim.x + threadIdx.x;
    if (e < EE) atomicAdd(&g_deg[ecol[e]], 1);
}

// Block-local exclusive scan of (deg-1) + dinv computation.
__global__ void scan1_kernel() {
    __shared__ int sbuf[1024];
    int t = threadIdx.x;
    int idx = blockIdx.x * 1024 + t;
    int d = (idx < NN) ? g_deg[idx] : 1;
    if (idx < NN) g_dinv[idx] = rsqrtf((float)d);
    int v = d - 1;                                  // real in-edges only
    sbuf[t] = v;
    __syncthreads();
    for (int off = 1; off < 1024; off <<= 1) {
        int tmp = (t >= off) ? sbuf[t - off] : 0;
        __syncthreads();
        sbuf[t] += tmp;
        __syncthreads();
    }
    if (idx < NN) g_rowptr[idx] = sbuf[t] - v;      // exclusive within block
    if (t == 1023) g_bsum[blockIdx.x] = sbuf[1023];
}

__global__ void scan2_kernel(int nb) {
    if (threadIdx.x == 0) {
        int acc = 0;
        for (int b = 0; b < nb; b++) { int v = g_bsum[b]; g_bsum[b] = acc; acc += v; }
    }
}

__global__ void scan3_kernel() {
    int idx = blockIdx.x * blockDim.x + threadIdx.x;
    if (idx < NN) {
        int rp = g_rowptr[idx] + g_bsum[idx >> 10];
        g_rowptr[idx] = rp;
        g_cursor[idx] = rp;
    }
    if (idx == 0) g_rowptr[NN] = EE;
}

__global__ void csr_kernel(const int* __restrict__ erow, const int* __restrict__ ecol) {
    int e = blockIdx.x * blockDim.x + threadIdx.x;
    if (e < EE) {
        int c = ecol[e];
        int pos = atomicAdd(&g_cursor[c], 1);
        g_csr[pos] = erow[e];
    }
}

// ------------------------------ GEMM --------------------------------------
// Warp per node: t[node] = h[node] @ W, W staged in shared, input row
// distributed across lanes and broadcast via shfl.
template <int K, bool FROM_GH>
__global__ void gemm_kernel(const float* __restrict__ hin, const float* __restrict__ W) {
    __shared__ float Ws[K * HF];
    for (int i = threadIdx.x; i < K * HF; i += blockDim.x) Ws[i] = W[i];
    __syncthreads();
    int lane = threadIdx.x & 31;
    int warp = (blockIdx.x * blockDim.x + threadIdx.x) >> 5;
    int nw   = (gridDim.x * blockDim.x) >> 5;
    const float* src = FROM_GH ? g_h : hin;
    for (int node = warp; node < NN; node += nw) {
        const float* hr = src + (size_t)node * K;
        float m0 = (K > 32 || lane < K) ? hr[lane] : 0.f;
        float m1 = (K > 32) ? hr[lane + 32] : 0.f;
        float a0 = 0.f, a1 = 0.f;
#pragma unroll
        for (int k = 0; k < K; k++) {
            float hv = (k < 32) ? __shfl_sync(0xffffffffu, m0, k)
                                : __shfl_sync(0xffffffffu, m1, k - 32);
            a0 = fmaf(hv, Ws[k * HF + lane], a0);
            a1 = fmaf(hv, Ws[k * HF + lane + 32], a1);
        }
        g_t[(size_t)node * HF + lane]      = a0;
        g_t[(size_t)node * HF + lane + 32] = a1;
    }
}

// --------------------------- aggregate ------------------------------------
// Warp per target node: acc = dinv_i^2 * t[i] + sum_{j in in(i)} dinv_j*dinv_i*t[j]
// then fused bias+BN(eval)+ReLU. Last layer also feeds pooling atomics.
__global__ void agg_kernel(const float* __restrict__ bias,
                           const float* __restrict__ bng, const float* __restrict__ bnb,
                           const float* __restrict__ bnm, const float* __restrict__ bnv,
                           int layer, int do_pool, const int* __restrict__ batch) {
    int lane = threadIdx.x & 31;
    int warp = (blockIdx.x * blockDim.x + threadIdx.x) >> 5;
    int nw   = (gridDim.x * blockDim.x) >> 5;
    int o = layer * HF;
    float sc0 = bng[o + lane]      * rsqrtf(bnv[o + lane]      + EPSV);
    float sc1 = bng[o + lane + 32] * rsqrtf(bnv[o + lane + 32] + EPSV);
    float sh0 = (bias[lane]      - bnm[o + lane])      * sc0 + bnb[o + lane];
    float sh1 = (bias[lane + 32] - bnm[o + lane + 32]) * sc1 + bnb[o + lane + 32];

    for (int i = warp; i < NN; i += nw) {
        float di = g_dinv[i];
        const float* ti = g_t + (size_t)i * HF;
        float a0 = di * di * ti[lane];
        float a1 = di * di * ti[lane + 32];
        int e = g_rowptr[i], end = g_rowptr[i + 1];
        if (e < end) {
            int s = __ldg(&g_csr[e]);
            float ds = __ldg(&g_dinv[s]);
            while (1) {
                const float* ts = g_t + (size_t)s * HF;
                float t0 = __ldg(ts + lane);
                float t1 = __ldg(ts + lane + 32);
                float w = ds * di;
                e++;
                if (e < end) {                       // prefetch next edge
                    s = __ldg(&g_csr[e]);
                    ds = __ldg(&g_dinv[s]);
                }
                a0 = fmaf(w, t0, a0);
                a1 = fmaf(w, t1, a1);
                if (e >= end) break;
            }
        }
        a0 = fmaxf(fmaf(a0, sc0, sh0), 0.f);
        a1 = fmaxf(fmaf(a1, sc1, sh1), 0.f);
        g_h[(size_t)i * HF + lane]      = a0;
        g_h[(size_t)i * HF + lane + 32] = a1;
        if (do_pool) {
            int g = batch[i];
            atomicAdd(&g_psum[g * HF + lane], a0);
            atomicAdd(&g_psum[g * HF + lane + 32], a1);
            atomicMax(&g_pmax[g * HF + lane], __float_as_uint(a0));       // a>=0
            atomicMax(&g_pmax[g * HF + lane + 32], __float_as_uint(a1));
            if (lane == 0) atomicAdd(&g_pcnt[g], 1);
        }
    }
}

// ------------------------------ head ---------------------------------------
// Warp per graph: pooled[128] = [mean(64) | max(64)]; hid = relu(pooled@Wc1+bc1);
// out = hid@Wc2+bc2.
__global__ void mlp_kernel(const float* __restrict__ Wc1, const float* __restrict__ bc1,
                           const float* __restrict__ Wc2, const float* __restrict__ bc2,
                           float* __restrict__ out) {
    int lane = threadIdx.x & 31;
    int g = (blockIdx.x * blockDim.x + threadIdx.x) >> 5;
    if (g >= GG) return;
    float inv = 1.0f / fmaxf((float)g_pcnt[g], 1.0f);
    float p0 = g_psum[g * HF + lane]      * inv;           // mean[lane]
    float p1 = g_psum[g * HF + lane + 32] * inv;           // mean[lane+32]
    float p2 = __uint_as_float(g_pmax[g * HF + lane]);     // max[lane]
    float p3 = __uint_as_float(g_pmax[g * HF + lane + 32]);// max[lane+32]
    float h0 = bc1[lane], h1 = bc1[lane + 32];
#pragma unroll
    for (int k = 0; k < 32; k++) {
        float v0 = __shfl_sync(0xffffffffu, p0, k);
        float v1 = __shfl_sync(0xffffffffu, p1, k);
        float v2 = __shfl_sync(0xffffffffu, p2, k);
        float v3 = __shfl_sync(0xffffffffu, p3, k);
        h0 = fmaf(v0, Wc1[k * HF + lane], h0);
        h0 = fmaf(v1, Wc1[(k + 32) * HF + lane], h0);
        h0 = fmaf(v2, Wc1[(k + 64) * HF + lane], h0);
        h0 = fmaf(v3, Wc1[(k + 96) * HF + lane], h0);
        h1 = fmaf(v0, Wc1[k * HF + lane + 32], h1);
        h1 = fmaf(v1, Wc1[(k + 32) * HF + lane + 32], h1);
        h1 = fmaf(v2, Wc1[(k + 64) * HF + lane + 32], h1);
        h1 = fmaf(v3, Wc1[(k + 96) * HF + lane + 32], h1);
    }
    h0 = fmaxf(h0, 0.f);
    h1 = fmaxf(h1, 0.f);
    float o0 = h0 * Wc2[lane * 2 + 0] + h1 * Wc2[(lane + 32) * 2 + 0];
    float o1 = h0 * Wc2[lane * 2 + 1] + h1 * Wc2[(lane + 32) * 2 + 1];
#pragma unroll
    for (int off = 16; off; off >>= 1) {
        o0 += __shfl_down_sync(0xffffffffu, o0, off);
        o1 += __shfl_down_sync(0xffffffffu, o1, off);
    }
    if (lane == 0) {
        out[g * 2 + 0] = o0 + bc2[0];
        out[g * 2 + 1] = o1 + bc2[1];
    }
}

// ------------------------------ launch -------------------------------------

extern "C" void kernel_launch(void* const* d_in, const int* in_sizes, int n_in,
                              void* d_out, int out_size) {
    const float* x    = (const float*)d_in[0];
    const int*   erow = (const int*)d_in[1];
    const int*   ecol = (const int*)d_in[2];
    const int*   batch= (const int*)d_in[3];
    const float* W0   = (const float*)d_in[4];
    const float* b0   = (const float*)d_in[5];
    const float* W1   = (const float*)d_in[6];
    const float* b1   = (const float*)d_in[7];
    const float* W2   = (const float*)d_in[8];
    const float* b2   = (const float*)d_in[9];
    const float* bng  = (const float*)d_in[10];
    const float* bnb  = (const float*)d_in[11];
    const float* bnm  = (const float*)d_in[12];
    const float* bnv  = (const float*)d_in[13];
    const float* Wc1  = (const float*)d_in[14];
    const float* bc1  = (const float*)d_in[15];
    const float* Wc2  = (const float*)d_in[16];
    const float* bc2  = (const float*)d_in[17];
    float* out = (float*)d_out;

    // graph structure (recomputed every call; all-int, cheap)
    init_kernel<<<(NN + 255) / 256, 256>>>();
    deg_kernel<<<(EE + 255) / 256, 256>>>(ecol);
    scan1_kernel<<<(NN + 1023) / 1024, 1024>>>();
    scan2_kernel<<<1, 32>>>((NN + 1023) / 1024);
    scan3_kernel<<<(NN + 255) / 256, 256>>>();
    csr_kernel<<<(EE + 255) / 256, 256>>>(erow, ecol);

    const int GB = 2048, BT = 256;
    gemm_kernel<INF, false><<<GB, BT>>>(x, W0);
    agg_kernel<<<GB, BT>>>(b0, bng, bnb, bnm, bnv, 0, 0, batch);
    gemm_kernel<HF, true><<<GB, BT>>>(nullptr, W1);
    agg_kernel<<<GB, BT>>>(b1, bng, bnb, bnm, bnv, 1, 0, batch);
    gemm_kernel<HF, true><<<GB, BT>>>(nullptr, W2);
    agg_kernel<<<GB, BT>>>(b2, bng, bnb, bnm, bnv, 2, 1, batch);
    mlp_kernel<<<(GG * 32 + 255) / 256, 256>>>(Wc1, bc1, Wc2, bc2, out);
}